// round 3
// baseline (speedup 1.0000x reference)
#include <cuda_runtime.h>
#include <math.h>

#define HC 64
#define NF 64
#define NG 5
#define SL 20
#define ZD 148
#define BN_EPS 1e-5f
#define MAX_N 50000
#define MAX_E 800000

typedef unsigned long long ull;

// Scratch (allocation-free rule: __device__ globals)
__device__ __align__(16) float g_agg[MAX_N * NF];        // per-layer aggregation
__device__ __align__(16) float g_proj[MAX_N * 4 * NF];   // [N][Af|Bf|As|Bs]
__device__ __align__(16) float g_ea[(size_t)MAX_E * SL]; // relu(edge_attr@short_w)
__device__ __align__(16) float g_sums[2 * NF];           // sum / sumsq

// ---------------- packed f32x2 helpers ----------------
__device__ __forceinline__ ull fma2(ull a, ull b, ull c) {
    ull d;
    asm("fma.rn.f32x2 %0, %1, %2, %3;" : "=l"(d) : "l"(a), "l"(b), "l"(c));
    return d;
}
__device__ __forceinline__ ull add2(ull a, ull b) {
    ull d;
    asm("add.rn.f32x2 %0, %1, %2;" : "=l"(d) : "l"(a), "l"(b));
    return d;
}
__device__ __forceinline__ ull pack2(float v) {
    ull r;
    asm("mov.b64 %0, {%1, %1};" : "=l"(r) : "f"(v));
    return r;
}
__device__ __forceinline__ float2 unpack2(ull v) {
    float2 r;
    asm("mov.b64 {%0, %1}, %2;" : "=f"(r.x), "=f"(r.y) : "l"(v));
    return r;
}
__device__ __forceinline__ void red_add_v2(float* addr, float a, float b) {
    asm volatile("red.global.add.v2.f32 [%0], {%1, %2};"
                 :: "l"(addr), "f"(a), "f"(b) : "memory");
}
__device__ __forceinline__ float msg_fn(float f, float s) {
    float sig = __fdividef(1.f, 1.f + __expf(-f));
    float sp  = fmaxf(s, 0.f) + __logf(1.f + __expf(-fabsf(s)));
    return sig * sp;
}

// ---------------------------------------------------------------------------
__global__ __launch_bounds__(256) void zero_kernel(int n4) {
    float4 z = make_float4(0.f, 0.f, 0.f, 0.f);
    float4* a = (float4*)g_agg;
    int stride = gridDim.x * blockDim.x;
    for (int i = blockIdx.x * blockDim.x + threadIdx.x; i < n4; i += stride) a[i] = z;
    if (blockIdx.x == 0 && threadIdx.x < 2 * NF) g_sums[threadIdx.x] = 0.f;
}

// ---------------------------------------------------------------------------
// g_ea = relu(edge_attr @ short_w + short_b)   (layer-invariant, computed once)
__global__ __launch_bounds__(256) void ea_kernel(
    const float* __restrict__ attr, const float* __restrict__ sw,
    const float* __restrict__ sb, int E)
{
    __shared__ float w[NG * SL];
    __shared__ float b[SL];
    int tid = threadIdx.x;
    if (tid < NG * SL) w[tid] = sw[tid];
    if (tid < SL)      b[tid] = sb[tid];
    __syncthreads();
    int stride = gridDim.x * blockDim.x;
    for (int e = blockIdx.x * blockDim.x + tid; e < E; e += stride) {
        float a[NG];
#pragma unroll
        for (int g = 0; g < NG; g++) a[g] = __ldg(attr + (size_t)e * NG + g);
        float4* dst = (float4*)(g_ea + (size_t)e * SL);
#pragma unroll
        for (int q = 0; q < 5; q++) {
            float o[4];
#pragma unroll
            for (int j = 0; j < 4; j++) {
                float acc = b[q * 4 + j];
#pragma unroll
                for (int g = 0; g < NG; g++)
                    acc = fmaf(a[g], w[g * SL + q * 4 + j], acc);
                o[j] = fmaxf(acc, 0.f);
            }
            dst[q] = make_float4(o[0], o[1], o[2], o[3]);
        }
    }
}

// ---------------------------------------------------------------------------
// out = relu(h @ W + b)   [N,64]
__global__ __launch_bounds__(256) void lin0_kernel(
    const float* __restrict__ h, const float* __restrict__ W,
    const float* __restrict__ b, float* __restrict__ out, int N)
{
    __shared__ float sW[64 * 64];
    __shared__ float sb[64];
    int tid = threadIdx.x;
    for (int i = tid; i < 64 * 64; i += 256) sW[i] = W[i];
    if (tid < 64) sb[tid] = b[tid];
    __syncthreads();

    int c = tid & 63, rr = tid >> 6;
    for (int r0 = blockIdx.x * 4; r0 < N; r0 += gridDim.x * 4) {
        int r = r0 + rr;
        if (r < N) {
            const float* hr = h + (size_t)r * 64;
            float acc = sb[c];
#pragma unroll 16
            for (int k = 0; k < 64; k++)
                acc = fmaf(__ldg(hr + k), sW[k * 64 + c], acc);
            out[(size_t)r * 64 + c] = fmaxf(acc, 0.f);
        }
    }
}

// ---------------------------------------------------------------------------
// g_proj[n] = out[n] @ [W1f | W2f | W1s | W2s]  (+bf on cols 0-63, +bs on 128-191)
__global__ __launch_bounds__(256) void node_proj_kernel(
    const float* __restrict__ out,
    const float* __restrict__ Wf, const float* __restrict__ bf,
    const float* __restrict__ Ws, const float* __restrict__ bs,
    int N)
{
    __shared__ __align__(16) float sOut[16 * 64];
    int tid = threadIdx.x;
    int c = tid;
    const float* base; int col; float bias;
    if (c < 64)       { base = Wf;           col = c;        bias = __ldg(bf + c); }
    else if (c < 128) { base = Wf + 64 * 64; col = c - 64;   bias = 0.f; }
    else if (c < 192) { base = Ws;           col = c - 128;  bias = __ldg(bs + c - 128); }
    else              { base = Ws + 64 * 64; col = c - 192;  bias = 0.f; }
    float w[64];
#pragma unroll
    for (int k = 0; k < 64; k++) w[k] = __ldg(base + k * 64 + col);

    for (int r0 = blockIdx.x * 16; r0 < N; r0 += gridDim.x * 16) {
        __syncthreads();
        for (int i = tid; i < 16 * 16; i += 256) {
            int r = i >> 4, q = i & 15;
            int rr = r0 + r;
            float4 v = (rr < N) ? ((const float4*)out)[(size_t)rr * 16 + q]
                                : make_float4(0.f, 0.f, 0.f, 0.f);
            ((float4*)sOut)[r * 16 + q] = v;
        }
        __syncthreads();
        float acc[16];
#pragma unroll
        for (int r = 0; r < 16; r++) acc[r] = bias;
#pragma unroll
        for (int k4 = 0; k4 < 16; k4++) {
#pragma unroll
            for (int r = 0; r < 16; r++) {
                float4 z = ((const float4*)sOut)[r * 16 + k4];
                acc[r] = fmaf(z.x, w[k4 * 4 + 0], acc[r]);
                acc[r] = fmaf(z.y, w[k4 * 4 + 1], acc[r]);
                acc[r] = fmaf(z.z, w[k4 * 4 + 2], acc[r]);
                acc[r] = fmaf(z.w, w[k4 * 4 + 3], acc[r]);
            }
        }
#pragma unroll
        for (int r = 0; r < 16; r++) {
            int rr = r0 + r;
            if (rr < N) g_proj[(size_t)rr * 256 + c] = acc[r];
        }
    }
}

// ---------------------------------------------------------------------------
// Edge kernel: 1 warp = 2 edges per iteration, lane owns channels 2*lane..2*lane+1.
// ea@W3 weights live entirely in REGISTERS (f32x2 packed) — zero smem traffic.
// f = Af[dst] + Bf[src] + ea@W3f ; s = As[dst] + Bs[src] + ea@W3s
// msg = sigmoid(f)*softplus(s); red.v2 into g_agg[dst].
__global__ __launch_bounds__(128) void edge_kernel(
    const int* __restrict__ ei,
    const float* __restrict__ W3f, const float* __restrict__ W3s,
    int E)
{
    int lane = threadIdx.x & 31;
    int c2 = lane * 2;

    // per-lane weight columns, packed as f32x2 (coalesced LDG.64 loads)
    ull wf[SL], ws[SL];
#pragma unroll
    for (int k = 0; k < SL; k++) {
        wf[k] = __ldg((const ull*)(W3f + k * 64 + c2));
        ws[k] = __ldg((const ull*)(W3s + k * 64 + c2));
    }

    long warp  = ((long)blockIdx.x * blockDim.x + threadIdx.x) >> 5;
    long nwarp = ((long)gridDim.x * blockDim.x) >> 5;
    long npairs = ((long)E + 1) >> 1;

    for (long p = warp; p < npairs; p += nwarp) {
        long e0 = 2 * p, e1 = e0 + 1;
        bool v1 = (e1 < E);
        long e1c = v1 ? e1 : e0;

        int s0 = __ldg(ei + e0),  d0 = __ldg(ei + E + e0);
        int s1 = __ldg(ei + e1c), d1 = __ldg(ei + E + e1c);

        const ull* p0d = (const ull*)(g_proj + (size_t)d0 * 256);
        const ull* p0s = (const ull*)(g_proj + (size_t)s0 * 256);
        const ull* p1d = (const ull*)(g_proj + (size_t)d1 * 256);
        const ull* p1s = (const ull*)(g_proj + (size_t)s1 * 256);

        // segments in ull units: Af 0-31 | Bf 32-63 | As 64-95 | Bs 96-127
        ull f0 = add2(__ldg(p0d + lane),      __ldg(p0s + 32 + lane));
        ull q0 = add2(__ldg(p0d + 64 + lane), __ldg(p0s + 96 + lane));
        ull f1 = add2(__ldg(p1d + lane),      __ldg(p1s + 32 + lane));
        ull q1 = add2(__ldg(p1d + 64 + lane), __ldg(p1s + 96 + lane));

        const float* ea0 = g_ea + e0  * SL;
        const float* ea1 = g_ea + e1c * SL;
#pragma unroll
        for (int k = 0; k < SL; k++) {
            ull a0 = pack2(__ldg(ea0 + k));
            ull a1 = pack2(__ldg(ea1 + k));
            f0 = fma2(a0, wf[k], f0);
            q0 = fma2(a0, ws[k], q0);
            f1 = fma2(a1, wf[k], f1);
            q1 = fma2(a1, ws[k], q1);
        }

        float2 F0 = unpack2(f0), Q0 = unpack2(q0);
        float m00 = msg_fn(F0.x, Q0.x);
        float m01 = msg_fn(F0.y, Q0.y);
        red_add_v2(&g_agg[(size_t)d0 * 64 + c2], m00, m01);
        if (v1) {
            float2 F1 = unpack2(f1), Q1 = unpack2(q1);
            float m10 = msg_fn(F1.x, Q1.x);
            float m11 = msg_fn(F1.y, Q1.y);
            red_add_v2(&g_agg[(size_t)d1 * 64 + c2], m10, m11);
        }
    }
}

// ---------------------------------------------------------------------------
__global__ __launch_bounds__(256) void bn_stats_kernel(int N) {
    __shared__ float4 s1[256], s2[256];
    int tid = threadIdx.x;
    const float4* a4 = (const float4*)g_agg;
    int total = N * 16;
    float4 s = make_float4(0.f, 0.f, 0.f, 0.f);
    float4 q = make_float4(0.f, 0.f, 0.f, 0.f);
    int stride = gridDim.x * 256;
    for (int i = blockIdx.x * 256 + tid; i < total; i += stride) {
        float4 v = a4[i];
        s.x += v.x; s.y += v.y; s.z += v.z; s.w += v.w;
        q.x = fmaf(v.x, v.x, q.x); q.y = fmaf(v.y, v.y, q.y);
        q.z = fmaf(v.z, v.z, q.z); q.w = fmaf(v.w, v.w, q.w);
    }
    s1[tid] = s; s2[tid] = q;
    __syncthreads();
    if (tid < 16) {
        float4 S = s1[tid], Q = s2[tid];
#pragma unroll
        for (int j = 1; j < 16; j++) {
            float4 a = s1[tid + 16 * j], b = s2[tid + 16 * j];
            S.x += a.x; S.y += a.y; S.z += a.z; S.w += a.w;
            Q.x += b.x; Q.y += b.y; Q.z += b.z; Q.w += b.w;
        }
        int c0 = tid * 4;
        atomicAdd(&g_sums[c0 + 0], S.x);
        atomicAdd(&g_sums[c0 + 1], S.y);
        atomicAdd(&g_sums[c0 + 2], S.z);
        atomicAdd(&g_sums[c0 + 3], S.w);
        atomicAdd(&g_sums[64 + c0 + 0], Q.x);
        atomicAdd(&g_sums[64 + c0 + 1], Q.y);
        atomicAdd(&g_sums[64 + c0 + 2], Q.z);
        atomicAdd(&g_sums[64 + c0 + 3], Q.w);
    }
}

// ---------------------------------------------------------------------------
// out = out + relu( BN(agg) + out )
__global__ __launch_bounds__(256) void bn_apply_kernel(
    const float* __restrict__ gamma, const float* __restrict__ beta,
    float* __restrict__ out, int N, float invN)
{
    int tid = threadIdx.x;
    int c0 = (tid & 15) * 4;
    float mul[4], add[4];
#pragma unroll
    for (int j = 0; j < 4; j++) {
        float mean = g_sums[c0 + j] * invN;
        float var  = fmaf(-mean, mean, g_sums[64 + c0 + j] * invN);
        float inv  = rsqrtf(var + BN_EPS);
        float m = inv * __ldg(gamma + c0 + j);
        mul[j] = m;
        add[j] = __ldg(beta + c0 + j) - mean * m;
    }
    float4* o4 = (float4*)out;
    const float4* a4 = (const float4*)g_agg;
    int total = N * 16;
    int stride = gridDim.x * 256;
    for (int i = blockIdx.x * 256 + tid; i < total; i += stride) {
        float4 a = a4[i], o = o4[i], r;
        float bn;
        bn = fmaf(a.x, mul[0], add[0]); r.x = o.x + fmaxf(bn + o.x, 0.f);
        bn = fmaf(a.y, mul[1], add[1]); r.y = o.y + fmaxf(bn + o.y, 0.f);
        bn = fmaf(a.z, mul[2], add[2]); r.z = o.z + fmaxf(bn + o.z, 0.f);
        bn = fmaf(a.w, mul[3], add[3]); r.w = o.w + fmaxf(bn + o.w, 0.f);
        o4[i] = r;
    }
}

// ---------------------------------------------------------------------------
extern "C" void kernel_launch(void* const* d_in, const int* in_sizes, int n_in,
                              void* d_out, int out_size)
{
    const float* h      = (const float*)d_in[0];
    const int*   ei     = (const int*)  d_in[1];
    // d_in[2] = edge_weight (unused by reference)
    const float* eattr  = (const float*)d_in[3];
    const float* lin0_w = (const float*)d_in[4];
    const float* lin0_b = (const float*)d_in[5];
    const float* shw    = (const float*)d_in[6];
    const float* shb    = (const float*)d_in[7];
    const float* linf_w = (const float*)d_in[8];
    const float* linf_b = (const float*)d_in[9];
    const float* lins_w = (const float*)d_in[10];
    const float* lins_b = (const float*)d_in[11];
    const float* gamma  = (const float*)d_in[12];
    const float* beta   = (const float*)d_in[13];

    int N = in_sizes[0] / HC;
    int E = in_sizes[1] / 2;
    float* out = (float*)d_out;

    ea_kernel<<<1184, 256>>>(eattr, shw, shb, E);
    lin0_kernel<<<592, 256>>>(h, lin0_w, lin0_b, out, N);

    for (int l = 0; l < 2; l++) {
        const float* Wf = linf_w + (size_t)l * ZD * NF;
        const float* Ws = lins_w + (size_t)l * ZD * NF;
        zero_kernel<<<592, 256>>>(N * 16);
        node_proj_kernel<<<592, 256>>>(out, Wf, linf_b + l * NF,
                                       Ws, lins_b + l * NF, N);
        edge_kernel<<<444, 128>>>(ei, Wf + 128 * NF, Ws + 128 * NF, E);
        bn_stats_kernel<<<592, 256>>>(N);
        bn_apply_kernel<<<592, 256>>>(gamma + l * NF, beta + l * NF, out, N, 1.f / (float)N);
    }
}

// round 4
// speedup vs baseline: 1.0153x; 1.0153x over previous
#include <cuda_runtime.h>
#include <math.h>

#define HC 64
#define NF 64
#define NG 5
#define SL 20
#define ZD 148
#define BN_EPS 1e-5f
#define MAX_N 50000
#define MAX_E 800000

typedef unsigned long long ull;

// Scratch (allocation-free rule: __device__ globals)
__device__ __align__(16) float g_agg[MAX_N * NF];        // per-layer aggregation
__device__ __align__(16) float g_proj[MAX_N * 4 * NF];   // [N][Af|Bf|As|Bs]
__device__ __align__(16) float g_ea[(size_t)MAX_E * SL]; // relu(edge_attr@short_w)
__device__ __align__(16) float g_sums[2 * NF];           // sum / sumsq
__device__ int  g_deg[MAX_N];
__device__ int  g_off[MAX_N];
__device__ int  g_cur[MAX_N];
__device__ __align__(8) int2 g_es[MAX_E];                // (src, edge_id) bucketed by dst

// ---------------- packed f32x2 helpers ----------------
__device__ __forceinline__ ull fma2(ull a, ull b, ull c) {
    ull d;
    asm("fma.rn.f32x2 %0, %1, %2, %3;" : "=l"(d) : "l"(a), "l"(b), "l"(c));
    return d;
}
__device__ __forceinline__ ull add2(ull a, ull b) {
    ull d;
    asm("add.rn.f32x2 %0, %1, %2;" : "=l"(d) : "l"(a), "l"(b));
    return d;
}
__device__ __forceinline__ ull pack2(float v) {
    ull r;
    asm("mov.b64 %0, {%1, %1};" : "=l"(r) : "f"(v));
    return r;
}
__device__ __forceinline__ float2 unpack2(ull v) {
    float2 r;
    asm("mov.b64 {%0, %1}, %2;" : "=f"(r.x), "=f"(r.y) : "l"(v));
    return r;
}
__device__ __forceinline__ float msg_fn(float f, float s) {
    float sig = __fdividef(1.f, 1.f + __expf(-f));
    float sp  = fmaxf(s, 0.f) + __logf(1.f + __expf(-fabsf(s)));
    return sig * sp;
}

// ---------------------------------------------------------------------------
// ---- edge bucketing (built once per call; reused by both layers) ----------
__global__ __launch_bounds__(256) void zero_deg_kernel(int N) {
    int stride = gridDim.x * blockDim.x;
    for (int i = blockIdx.x * blockDim.x + threadIdx.x; i < N; i += stride)
        g_deg[i] = 0;
}

__global__ __launch_bounds__(256) void hist_kernel(const int* __restrict__ ei, int E) {
    int stride = gridDim.x * blockDim.x;
    for (int e = blockIdx.x * blockDim.x + threadIdx.x; e < E; e += stride)
        atomicAdd(&g_deg[__ldg(ei + E + e)], 1);
}

__global__ __launch_bounds__(1024) void scan_kernel(int N) {
    __shared__ int part[1024];
    int t = threadIdx.x;
    int C = (N + 1023) >> 10;
    int lo = t * C, hi = min(lo + C, N);
    int s = 0;
    for (int i = lo; i < hi; i++) s += g_deg[i];
    part[t] = s;
    __syncthreads();
    for (int d = 1; d < 1024; d <<= 1) {
        int v = (t >= d) ? part[t - d] : 0;
        __syncthreads();
        part[t] += v;
        __syncthreads();
    }
    int run = part[t] - s;  // exclusive prefix for this chunk
    for (int i = lo; i < hi; i++) {
        int d = g_deg[i];
        g_off[i] = run;
        g_cur[i] = run;
        run += d;
    }
}

__global__ __launch_bounds__(256) void scatter_kernel(const int* __restrict__ ei, int E) {
    int stride = gridDim.x * blockDim.x;
    for (int e = blockIdx.x * blockDim.x + threadIdx.x; e < E; e += stride) {
        int dst = __ldg(ei + E + e);
        int pos = atomicAdd(&g_cur[dst], 1);
        g_es[pos] = make_int2(__ldg(ei + e), e);
    }
}

// ---------------------------------------------------------------------------
// g_ea = relu(edge_attr @ short_w + short_b)   (layer-invariant, computed once)
__global__ __launch_bounds__(256) void ea_kernel(
    const float* __restrict__ attr, const float* __restrict__ sw,
    const float* __restrict__ sb, int E)
{
    __shared__ float w[NG * SL];
    __shared__ float b[SL];
    int tid = threadIdx.x;
    if (tid < NG * SL) w[tid] = sw[tid];
    if (tid < SL)      b[tid] = sb[tid];
    __syncthreads();
    int stride = gridDim.x * blockDim.x;
    for (int e = blockIdx.x * blockDim.x + tid; e < E; e += stride) {
        float a[NG];
#pragma unroll
        for (int g = 0; g < NG; g++) a[g] = __ldg(attr + (size_t)e * NG + g);
        float4* dst = (float4*)(g_ea + (size_t)e * SL);
#pragma unroll
        for (int q = 0; q < 5; q++) {
            float o[4];
#pragma unroll
            for (int j = 0; j < 4; j++) {
                float acc = b[q * 4 + j];
#pragma unroll
                for (int g = 0; g < NG; g++)
                    acc = fmaf(a[g], w[g * SL + q * 4 + j], acc);
                o[j] = fmaxf(acc, 0.f);
            }
            dst[q] = make_float4(o[0], o[1], o[2], o[3]);
        }
    }
}

// ---------------------------------------------------------------------------
// out = relu(h @ W + b)   [N,64]
__global__ __launch_bounds__(256) void lin0_kernel(
    const float* __restrict__ h, const float* __restrict__ W,
    const float* __restrict__ b, float* __restrict__ out, int N)
{
    __shared__ float sW[64 * 64];
    __shared__ float sb[64];
    int tid = threadIdx.x;
    for (int i = tid; i < 64 * 64; i += 256) sW[i] = W[i];
    if (tid < 64) sb[tid] = b[tid];
    __syncthreads();

    int c = tid & 63, rr = tid >> 6;
    for (int r0 = blockIdx.x * 4; r0 < N; r0 += gridDim.x * 4) {
        int r = r0 + rr;
        if (r < N) {
            const float* hr = h + (size_t)r * 64;
            float acc = sb[c];
#pragma unroll 16
            for (int k = 0; k < 64; k++)
                acc = fmaf(__ldg(hr + k), sW[k * 64 + c], acc);
            out[(size_t)r * 64 + c] = fmaxf(acc, 0.f);
        }
    }
}

// ---------------------------------------------------------------------------
// g_proj[n] = out[n] @ [W1f | W2f | W1s | W2s]  (+bf on cols 0-63, +bs on 128-191)
__global__ __launch_bounds__(256) void node_proj_kernel(
    const float* __restrict__ out,
    const float* __restrict__ Wf, const float* __restrict__ bf,
    const float* __restrict__ Ws, const float* __restrict__ bs,
    int N)
{
    __shared__ __align__(16) float sOut[16 * 64];
    int tid = threadIdx.x;
    int c = tid;
    const float* base; int col; float bias;
    if (c < 64)       { base = Wf;           col = c;        bias = __ldg(bf + c); }
    else if (c < 128) { base = Wf + 64 * 64; col = c - 64;   bias = 0.f; }
    else if (c < 192) { base = Ws;           col = c - 128;  bias = __ldg(bs + c - 128); }
    else              { base = Ws + 64 * 64; col = c - 192;  bias = 0.f; }
    float w[64];
#pragma unroll
    for (int k = 0; k < 64; k++) w[k] = __ldg(base + k * 64 + col);

    for (int r0 = blockIdx.x * 16; r0 < N; r0 += gridDim.x * 16) {
        __syncthreads();
        for (int i = tid; i < 16 * 16; i += 256) {
            int r = i >> 4, q = i & 15;
            int rr = r0 + r;
            float4 v = (rr < N) ? ((const float4*)out)[(size_t)rr * 16 + q]
                                : make_float4(0.f, 0.f, 0.f, 0.f);
            ((float4*)sOut)[r * 16 + q] = v;
        }
        __syncthreads();
        float acc[16];
#pragma unroll
        for (int r = 0; r < 16; r++) acc[r] = bias;
#pragma unroll
        for (int k4 = 0; k4 < 16; k4++) {
#pragma unroll
            for (int r = 0; r < 16; r++) {
                float4 z = ((const float4*)sOut)[r * 16 + k4];
                acc[r] = fmaf(z.x, w[k4 * 4 + 0], acc[r]);
                acc[r] = fmaf(z.y, w[k4 * 4 + 1], acc[r]);
                acc[r] = fmaf(z.z, w[k4 * 4 + 2], acc[r]);
                acc[r] = fmaf(z.w, w[k4 * 4 + 3], acc[r]);
            }
        }
#pragma unroll
        for (int r = 0; r < 16; r++) {
            int rr = r0 + r;
            if (rr < N) g_proj[(size_t)rr * 256 + c] = acc[r];
        }
    }
}

// ---------------------------------------------------------------------------
// Fused gather + aggregate: one warp per node (dst). No atomics, no agg zeroing.
// Lane owns channels 2*lane, 2*lane+1. ea@W3 weights in registers (f32x2).
// For each in-edge (src, eid):
//   f = Af[n] + Bf[src] + ea[eid]@W3f ; s = As[n] + Bs[src] + ea[eid]@W3s
//   acc += sigmoid(f) * softplus(s)
__global__ __launch_bounds__(128) void edge_agg_kernel(
    const float* __restrict__ W3f, const float* __restrict__ W3s, int N)
{
    int lane = threadIdx.x & 31;
    int c2 = lane * 2;

    ull wf[SL], ws[SL];
#pragma unroll
    for (int k = 0; k < SL; k++) {
        wf[k] = __ldg((const ull*)(W3f + k * 64 + c2));
        ws[k] = __ldg((const ull*)(W3s + k * 64 + c2));
    }

    int warp  = (blockIdx.x * 128 + threadIdx.x) >> 5;
    int nwarp = gridDim.x * 4;

    for (int n = warp; n < N; n += nwarp) {
        int beg = __ldg(&g_off[n]);
        int end = beg + __ldg(&g_deg[n]);

        const ull* pd = (const ull*)(g_proj + (size_t)n * 256);
        ull afd = __ldg(pd + lane);       // Af[n] (bias included)
        ull asd = __ldg(pd + 64 + lane);  // As[n] (bias included)

        float accx = 0.f, accy = 0.f;
        int i = beg;

        // 2 edges per iteration for MLP
        for (; i + 1 < end; i += 2) {
            int2 se0 = __ldg(&g_es[i]);
            int2 se1 = __ldg(&g_es[i + 1]);
            const ull* p0 = (const ull*)(g_proj + (size_t)se0.x * 256);
            const ull* p1 = (const ull*)(g_proj + (size_t)se1.x * 256);
            ull bf0 = __ldg(p0 + 32 + lane), bs0 = __ldg(p0 + 96 + lane);
            ull bf1 = __ldg(p1 + 32 + lane), bs1 = __ldg(p1 + 96 + lane);
            const float4* ea0 = (const float4*)(g_ea + (size_t)se0.y * SL);
            const float4* ea1 = (const float4*)(g_ea + (size_t)se1.y * SL);

            ull f0 = add2(afd, bf0), q0 = add2(asd, bs0);
            ull f1 = add2(afd, bf1), q1 = add2(asd, bs1);
#pragma unroll
            for (int kk = 0; kk < 5; kk++) {
                float4 A0 = __ldg(ea0 + kk);
                float4 A1 = __ldg(ea1 + kk);
                float a0v[4] = {A0.x, A0.y, A0.z, A0.w};
                float a1v[4] = {A1.x, A1.y, A1.z, A1.w};
#pragma unroll
                for (int j = 0; j < 4; j++) {
                    int k = kk * 4 + j;
                    ull a0 = pack2(a0v[j]);
                    ull a1 = pack2(a1v[j]);
                    f0 = fma2(a0, wf[k], f0);
                    q0 = fma2(a0, ws[k], q0);
                    f1 = fma2(a1, wf[k], f1);
                    q1 = fma2(a1, ws[k], q1);
                }
            }
            float2 F0 = unpack2(f0), Q0 = unpack2(q0);
            float2 F1 = unpack2(f1), Q1 = unpack2(q1);
            accx += msg_fn(F0.x, Q0.x) + msg_fn(F1.x, Q1.x);
            accy += msg_fn(F0.y, Q0.y) + msg_fn(F1.y, Q1.y);
        }
        if (i < end) {
            int2 se0 = __ldg(&g_es[i]);
            const ull* p0 = (const ull*)(g_proj + (size_t)se0.x * 256);
            ull bf0 = __ldg(p0 + 32 + lane), bs0 = __ldg(p0 + 96 + lane);
            const float4* ea0 = (const float4*)(g_ea + (size_t)se0.y * SL);
            ull f0 = add2(afd, bf0), q0 = add2(asd, bs0);
#pragma unroll
            for (int kk = 0; kk < 5; kk++) {
                float4 A0 = __ldg(ea0 + kk);
                float a0v[4] = {A0.x, A0.y, A0.z, A0.w};
#pragma unroll
                for (int j = 0; j < 4; j++) {
                    int k = kk * 4 + j;
                    ull a0 = pack2(a0v[j]);
                    f0 = fma2(a0, wf[k], f0);
                    q0 = fma2(a0, ws[k], q0);
                }
            }
            float2 F0 = unpack2(f0), Q0 = unpack2(q0);
            accx += msg_fn(F0.x, Q0.x);
            accy += msg_fn(F0.y, Q0.y);
        }

        *(float2*)&g_agg[(size_t)n * 64 + c2] = make_float2(accx, accy);
    }
}

// ---------------------------------------------------------------------------
__global__ void zero_sums_kernel() {
    if (threadIdx.x < 2 * NF) g_sums[threadIdx.x] = 0.f;
}

__global__ __launch_bounds__(256) void bn_stats_kernel(int N) {
    __shared__ float4 s1[256], s2[256];
    int tid = threadIdx.x;
    const float4* a4 = (const float4*)g_agg;
    int total = N * 16;
    float4 s = make_float4(0.f, 0.f, 0.f, 0.f);
    float4 q = make_float4(0.f, 0.f, 0.f, 0.f);
    int stride = gridDim.x * 256;
    for (int i = blockIdx.x * 256 + tid; i < total; i += stride) {
        float4 v = a4[i];
        s.x += v.x; s.y += v.y; s.z += v.z; s.w += v.w;
        q.x = fmaf(v.x, v.x, q.x); q.y = fmaf(v.y, v.y, q.y);
        q.z = fmaf(v.z, v.z, q.z); q.w = fmaf(v.w, v.w, q.w);
    }
    s1[tid] = s; s2[tid] = q;
    __syncthreads();
    if (tid < 16) {
        float4 S = s1[tid], Q = s2[tid];
#pragma unroll
        for (int j = 1; j < 16; j++) {
            float4 a = s1[tid + 16 * j], b = s2[tid + 16 * j];
            S.x += a.x; S.y += a.y; S.z += a.z; S.w += a.w;
            Q.x += b.x; Q.y += b.y; Q.z += b.z; Q.w += b.w;
        }
        int c0 = tid * 4;
        atomicAdd(&g_sums[c0 + 0], S.x);
        atomicAdd(&g_sums[c0 + 1], S.y);
        atomicAdd(&g_sums[c0 + 2], S.z);
        atomicAdd(&g_sums[c0 + 3], S.w);
        atomicAdd(&g_sums[64 + c0 + 0], Q.x);
        atomicAdd(&g_sums[64 + c0 + 1], Q.y);
        atomicAdd(&g_sums[64 + c0 + 2], Q.z);
        atomicAdd(&g_sums[64 + c0 + 3], Q.w);
    }
}

// ---------------------------------------------------------------------------
// out = out + relu( BN(agg) + out )
__global__ __launch_bounds__(256) void bn_apply_kernel(
    const float* __restrict__ gamma, const float* __restrict__ beta,
    float* __restrict__ out, int N, float invN)
{
    int tid = threadIdx.x;
    int c0 = (tid & 15) * 4;
    float mul[4], add[4];
#pragma unroll
    for (int j = 0; j < 4; j++) {
        float mean = g_sums[c0 + j] * invN;
        float var  = fmaf(-mean, mean, g_sums[64 + c0 + j] * invN);
        float inv  = rsqrtf(var + BN_EPS);
        float m = inv * __ldg(gamma + c0 + j);
        mul[j] = m;
        add[j] = __ldg(beta + c0 + j) - mean * m;
    }
    float4* o4 = (float4*)out;
    const float4* a4 = (const float4*)g_agg;
    int total = N * 16;
    int stride = gridDim.x * 256;
    for (int i = blockIdx.x * 256 + tid; i < total; i += stride) {
        float4 a = a4[i], o = o4[i], r;
        float bn;
        bn = fmaf(a.x, mul[0], add[0]); r.x = o.x + fmaxf(bn + o.x, 0.f);
        bn = fmaf(a.y, mul[1], add[1]); r.y = o.y + fmaxf(bn + o.y, 0.f);
        bn = fmaf(a.z, mul[2], add[2]); r.z = o.z + fmaxf(bn + o.z, 0.f);
        bn = fmaf(a.w, mul[3], add[3]); r.w = o.w + fmaxf(bn + o.w, 0.f);
        o4[i] = r;
    }
}

// ---------------------------------------------------------------------------
extern "C" void kernel_launch(void* const* d_in, const int* in_sizes, int n_in,
                              void* d_out, int out_size)
{
    const float* h      = (const float*)d_in[0];
    const int*   ei     = (const int*)  d_in[1];
    // d_in[2] = edge_weight (unused by reference)
    const float* eattr  = (const float*)d_in[3];
    const float* lin0_w = (const float*)d_in[4];
    const float* lin0_b = (const float*)d_in[5];
    const float* shw    = (const float*)d_in[6];
    const float* shb    = (const float*)d_in[7];
    const float* linf_w = (const float*)d_in[8];
    const float* linf_b = (const float*)d_in[9];
    const float* lins_w = (const float*)d_in[10];
    const float* lins_b = (const float*)d_in[11];
    const float* gamma  = (const float*)d_in[12];
    const float* beta   = (const float*)d_in[13];

    int N = in_sizes[0] / HC;
    int E = in_sizes[1] / 2;
    float* out = (float*)d_out;

    // once-per-call: edge bucketing by dst
    zero_deg_kernel<<<128, 256>>>(N);
    hist_kernel<<<1480, 256>>>(ei, E);
    scan_kernel<<<1, 1024>>>(N);
    scatter_kernel<<<1480, 256>>>(ei, E);

    ea_kernel<<<1480, 256>>>(eattr, shw, shb, E);
    lin0_kernel<<<592, 256>>>(h, lin0_w, lin0_b, out, N);

    int edge_blocks = (N + 3) / 4;  // 1 warp per node, 4 warps per block
    for (int l = 0; l < 2; l++) {
        const float* Wf = linf_w + (size_t)l * ZD * NF;
        const float* Ws = lins_w + (size_t)l * ZD * NF;
        node_proj_kernel<<<592, 256>>>(out, Wf, linf_b + l * NF,
                                       Ws, lins_b + l * NF, N);
        edge_agg_kernel<<<edge_blocks, 128>>>(Wf + 128 * NF, Ws + 128 * NF, N);
        zero_sums_kernel<<<1, 128>>>();
        bn_stats_kernel<<<592, 256>>>(N);
        bn_apply_kernel<<<592, 256>>>(gamma + l * NF, beta + l * NF, out, N, 1.f / (float)N);
    }
}